// round 1
// baseline (speedup 1.0000x reference)
#include <cuda_runtime.h>
#include <cuda_bf16.h>

// out[0,d,h,w,c] = in[0, z[d], row[h], col[w], 0]
// Shapes: in (1,128,128,128,32) f32; z/row/col (64,) i32; out (1,64,64,64,32) f32.
// One thread per output float4: 8 threads per (d,h,w), broadcast gather, coalesced writes.

__global__ __launch_bounds__(256) void sdown3d_kernel(
    const float* __restrict__ in,
    const int* __restrict__ zi,
    const int* __restrict__ ri,
    const int* __restrict__ ci,
    float4* __restrict__ out)
{
    int gid = blockIdx.x * blockDim.x + threadIdx.x;   // 0 .. 64^3*8 - 1
    int pos = gid >> 3;                                 // spatial position
    int w = pos & 63;
    int h = (pos >> 6) & 63;
    int d = pos >> 12;

    int src = ((__ldg(zi + d) << 7) + __ldg(ri + h));   // z*128 + row
    src = ((src << 7) + __ldg(ci + w)) << 5;            // (*128 + col) * 32

    float v = __ldg(in + src);
    out[gid] = make_float4(v, v, v, v);
}

extern "C" void kernel_launch(void* const* d_in, const int* in_sizes, int n_in,
                              void* d_out, int out_size)
{
    const float* in  = (const float*)d_in[0];
    const int*   zi  = (const int*)d_in[1];
    const int*   ri  = (const int*)d_in[2];
    const int*   ci  = (const int*)d_in[3];
    float4*      out = (float4*)d_out;

    // total output float4s: 64*64*64*32/4 = 2,097,152
    const int total = 64 * 64 * 64 * 8;
    const int threads = 256;
    const int blocks = total / threads;   // 8192
    sdown3d_kernel<<<blocks, threads>>>(in, zi, ri, ci, out);
}